// round 14
// baseline (speedup 1.0000x reference)
#include <cuda_runtime.h>
#include <cuda_fp16.h>

// Problem constants
#define NW 16384   // words
#define WL 16      // word length
#define D  300     // hidden dim
#define DP 320     // padded channel count (zeros in [300,320))
#define NL 128     // letters
#define KS 3       // conv taps

// Single persistent kernel: 296 blocks x 768 threads, 2 CTA/SM (all resident).
#define WPB 24
#define NTHREADS 768
#define B0 118
#define B1 118
#define B2 60
#define NBLOCKS (B0 + B1 + B2)          // 296 = 2 * 148
#define SMEM_BYTES (KS * NL * 128 * 2)  // 96 KB (encode table; phases reuse it)

// Device scratch
__device__ __half g_Ph[KS][NL][DP];  // per-letter conv partials (bias in k=1 tap)
__device__ float  g_embT[D * NL];    // emb transposed: [i][v]
__device__ uint4  g_wpk[NW];         // packed letters: 16 u8 per word

// Grid barrier (epoch-based, multi-replay safe: sense read before arrive;
// counter reset happens-before release).
__device__ volatile unsigned g_epoch = 0;
__device__ unsigned g_cnt = 0;

__device__ __forceinline__ void grid_barrier(int tid) {
    __syncthreads();
    if (tid == 0) {
        unsigned e0 = g_epoch;            // read sense BEFORE arriving
        __threadfence();                  // publish this block's global writes
        unsigned old = atomicAdd(&g_cnt, 1);
        if (old == NBLOCKS - 1) {
            g_cnt = 0;
            __threadfence();
            g_epoch = e0 + 1;             // release
        } else {
            while (g_epoch == e0) { __nanosleep(32); }
        }
        __threadfence();                  // acquire
    }
    __syncthreads();
}

#define GETL(l) ((lw[(l) >> 2] >> (((l) & 3) * 8)) & 0xFF)

#define INNER_BODY(loidx)                                                        \
    half2 m0 = NEGI, m1 = NEGI, m2 = NEGI, m3 = NEGI;                            \
    _Pragma("unroll")                                                            \
    for (int l = 0; l < WL; ++l) {                                               \
        uint4 a = Pv[(NL + GETL(l)) * 16 + (loidx)];                             \
        half2 h0 = *(half2*)&a.x, h1 = *(half2*)&a.y;                            \
        half2 h2 = *(half2*)&a.z, h3 = *(half2*)&a.w;                            \
        if (l > 0) {                                                             \
            uint4 q = Pv[GETL(l - 1) * 16 + (loidx)];                            \
            h0 = __hadd2(h0, *(half2*)&q.x); h1 = __hadd2(h1, *(half2*)&q.y);    \
            h2 = __hadd2(h2, *(half2*)&q.z); h3 = __hadd2(h3, *(half2*)&q.w);    \
        }                                                                        \
        if (l < WL - 1) {                                                        \
            uint4 q = Pv[(2 * NL + GETL(l + 1)) * 16 + (loidx)];                 \
            h0 = __hadd2(h0, *(half2*)&q.x); h1 = __hadd2(h1, *(half2*)&q.y);    \
            h2 = __hadd2(h2, *(half2*)&q.z); h3 = __hadd2(h3, *(half2*)&q.w);    \
        }                                                                        \
        m0 = __hmax2(m0, h0); m1 = __hmax2(m1, h1);                              \
        m2 = __hmax2(m2, h2); m3 = __hmax2(m3, h3);                              \
    }

__global__ __launch_bounds__(NTHREADS, 2) void fused_kernel(const int* __restrict__ words,
                                                            const float* __restrict__ emb,
                                                            const float* __restrict__ w,
                                                            const float* __restrict__ bias,
                                                            float* __restrict__ out) {
    extern __shared__ uint4 Pv[];  // 96 KB; earlier phases alias it
    const int b   = blockIdx.x;
    const int tid = threadIdx.x;

    // ================= PHASE 0: transpose emb + pack words =================
    if (b < 40) {
        // tiled transpose emb [128][300] -> embT [300][128]
        float* t = (float*)Pv;  // [32][33]
        const int bx = b % 10, by = b / 10;
        const int i0 = bx * 32, v0 = by * 32;
        if (tid < 256) {
            const int x = tid & 31, y = tid >> 5;  // 32 x 8
#pragma unroll
            for (int dy = 0; dy < 32; dy += 8) {
                int v = v0 + y + dy, i = i0 + x;
                t[(y + dy) * 33 + x] = (i < D) ? emb[v * D + i] : 0.f;
            }
        }
        __syncthreads();
        if (tid < 256) {
            const int x = tid & 31, y = tid >> 5;
#pragma unroll
            for (int dy = 0; dy < 32; dy += 8) {
                int i = i0 + y + dy, v = v0 + x;
                if (i < D) g_embT[i * NL + v] = t[x * 33 + (y + dy)];
            }
        }
    } else if (b < 62) {
        // pack letters: 22 blocks * 768 = 16896 >= 16384
        const int n = (b - 40) * NTHREADS + tid;
        if (n < NW) {
            unsigned r0 = 0, r1 = 0, r2 = 0, r3 = 0;
#pragma unroll
            for (int l = 0; l < 4; ++l)  r0 |= ((unsigned)words[l * NW + n] & 0xFF) << (l * 8);
#pragma unroll
            for (int l = 4; l < 8; ++l)  r1 |= ((unsigned)words[l * NW + n] & 0xFF) << ((l - 4) * 8);
#pragma unroll
            for (int l = 8; l < 12; ++l) r2 |= ((unsigned)words[l * NW + n] & 0xFF) << ((l - 8) * 8);
#pragma unroll
            for (int l = 12; l < 16; ++l) r3 |= ((unsigned)words[l * NW + n] & 0xFF) << ((l - 12) * 8);
            g_wpk[n] = make_uint4(r0, r1, r2, r3);
        }
    }

    grid_barrier(tid);

    // ================= PHASE 1: P build from embT (K-split x3) =============
    // 160 blocks, all 768 threads busy: thread (j, kt, v) computes channel
    // ob+j, letter v, over K-third [kt*100, kt*100+100). Partials combined
    // in smem; bias folded into the k=1 tap.
    if (b < 160) {
        float*  ws = (float*)Pv;                 // [2][KS][304] w rows
        float4* ps = (float4*)(ws + 2 * KS * 304);  // [2*3][128] partials

        const int ob = b * 2;
        const int j  = tid / 384;      // 0..1 (channel within block)
        const int u  = tid % 384;
        const int kt = u >> 7;         // 0..2 (K-third)
        const int v  = u & 127;        // letter
        const int o  = ob + j;         // 0..319

        for (int t = tid; t < 2 * D * KS; t += NTHREADS) {
            int jj = t / (D * KS), r = t % (D * KS);
            int oo = ob + jj;
            ws[(jj * KS + r % 3) * 304 + r / 3] = (oo < D) ? w[oo * D * KS + r] : 0.f;
        }
        __syncthreads();

        float a0 = 0.f, a1 = 0.f, a2 = 0.f;
        {
            const float* et  = g_embT + v;  // stride NL, coalesced across lanes
            const float* w0p = ws + (j * KS + 0) * 304;
            const float* w1p = ws + (j * KS + 1) * 304;
            const float* w2p = ws + (j * KS + 2) * 304;
            const int i0 = kt * 100;
#pragma unroll 5
            for (int i = i0; i < i0 + 100; i += 4) {
                float4 w0 = *(const float4*)(w0p + i);
                float4 w1 = *(const float4*)(w1p + i);
                float4 w2 = *(const float4*)(w2p + i);
                float e0 = et[(i + 0) * NL];
                float e1 = et[(i + 1) * NL];
                float e2 = et[(i + 2) * NL];
                float e3 = et[(i + 3) * NL];
                a0 = fmaf(e0, w0.x, a0); a1 = fmaf(e0, w1.x, a1); a2 = fmaf(e0, w2.x, a2);
                a0 = fmaf(e1, w0.y, a0); a1 = fmaf(e1, w1.y, a1); a2 = fmaf(e1, w2.y, a2);
                a0 = fmaf(e2, w0.z, a0); a1 = fmaf(e2, w1.z, a1); a2 = fmaf(e2, w2.z, a2);
                a0 = fmaf(e3, w0.w, a0); a1 = fmaf(e3, w1.w, a1); a2 = fmaf(e3, w2.w, a2);
            }
        }
        ps[(j * 3 + kt) * 128 + v] = make_float4(a0, a1, a2, 0.f);
        __syncthreads();

        if (kt == 0) {
            float4 x = ps[(j * 3 + 0) * 128 + v];
            float4 y = ps[(j * 3 + 1) * 128 + v];
            float4 z = ps[(j * 3 + 2) * 128 + v];
            float s0 = x.x + y.x + z.x;
            float s1 = x.y + y.y + z.y;
            float s2 = x.z + y.z + z.z;
            bool real = (o < D);
            float bv = real ? bias[o] : 0.f;
            g_Ph[0][v][o] = __float2half(real ? s0 : 0.f);
            g_Ph[1][v][o] = __float2half(real ? (s1 + bv) : 0.f);  // bias in k=1
            g_Ph[2][v][o] = __float2half(real ? s2 : 0.f);
        }
    }

    grid_barrier(tid);

    // ======================= PHASE 2: ENCODE =======================
    int slice, lb, nb;
    if (b < B0)           { slice = 0; lb = b;           nb = B0; }
    else if (b < B0 + B1) { slice = 1; lb = b - B0;      nb = B1; }
    else                  { slice = 2; lb = b - B0 - B1; nb = B2; }
    const int c0 = slice * 128;
    const int nchunk = (slice == 2) ? 8 : 16;

    const uint4* gP = (const uint4*)g_Ph;  // row stride DP/8 = 40 uint4
    for (int idx = tid; idx < KS * NL * nchunk; idx += NTHREADS) {
        int r = idx / nchunk, c = idx % nchunk;
        Pv[r * 16 + c] = gP[r * (DP / 8) + slice * 16 + c];
    }
    __syncthreads();

    const int lane  = tid & 31;
    const int wid   = tid >> 5;
    const int wsl   = lb * WPB + wid;
    const int nwarp = nb * WPB;

    const __half NH = __ushort_as_half((unsigned short)0xFC00);  // -inf
    const half2 NEGI = __halves2half2(NH, NH);

    if (slice < 2) {
        // ---- 128-ch slice: 2 words per warp (16-lane halves) ----
        const int lo   = lane & 15;
        const int half = lane >> 4;
        const int ch   = c0 + lo * 8;

        uint4 pk = g_wpk[2 * wsl + half];
        for (int p = wsl; p < NW / 2; p += nwarp) {
            const int pn = p + nwarp;
            uint4 nxt = make_uint4(0, 0, 0, 0);
            if (pn < NW / 2) nxt = g_wpk[2 * pn + half];

            unsigned lw[4] = {pk.x, pk.y, pk.z, pk.w};
            const int gw = 2 * p + half;

            INNER_BODY(lo)

            float2 f0 = __half22float2(m0), f1 = __half22float2(m1);
            float2 f2 = __half22float2(m2), f3 = __half22float2(m3);
            float* op = out + (size_t)gw * D + ch;
            float4 r;
            r.x = fmaxf(f0.x, 0.f); r.y = fmaxf(f0.y, 0.f);
            r.z = fmaxf(f1.x, 0.f); r.w = fmaxf(f1.y, 0.f);
            *(float4*)op = r;
            r.x = fmaxf(f2.x, 0.f); r.y = fmaxf(f2.y, 0.f);
            r.z = fmaxf(f3.x, 0.f); r.w = fmaxf(f3.y, 0.f);
            *(float4*)(op + 4) = r;

            pk = nxt;
        }
    } else {
        // ---- 64-ch slice (channels 256..299 real): 4 words per warp ----
        const int lo8 = lane & 7;
        const int g   = lane >> 3;
        const int ch  = c0 + lo8 * 8;  // 256..312

        uint4 pk = g_wpk[4 * wsl + g];
        for (int p = wsl; p < NW / 4; p += nwarp) {
            const int pn = p + nwarp;
            uint4 nxt = make_uint4(0, 0, 0, 0);
            if (pn < NW / 4) nxt = g_wpk[4 * pn + g];

            unsigned lw[4] = {pk.x, pk.y, pk.z, pk.w};
            const int gw = 4 * p + g;

            INNER_BODY(lo8)

            float2 f0 = __half22float2(m0), f1 = __half22float2(m1);
            float2 f2 = __half22float2(m2), f3 = __half22float2(m3);
            float* op = out + (size_t)gw * D + ch;
            if (ch < D) {
                float4 r;
                r.x = fmaxf(f0.x, 0.f); r.y = fmaxf(f0.y, 0.f);
                r.z = fmaxf(f1.x, 0.f); r.w = fmaxf(f1.y, 0.f);
                *(float4*)op = r;
            }
            if (ch + 4 < D) {
                float4 r;
                r.x = fmaxf(f2.x, 0.f); r.y = fmaxf(f2.y, 0.f);
                r.z = fmaxf(f3.x, 0.f); r.w = fmaxf(f3.y, 0.f);
                *(float4*)(op + 4) = r;
            }
            pk = nxt;
        }
    }
}

// ---------------------------------------------------------------------------
// Launch. Inputs: words(int32), emb(f32), conv_w(f32), conv_b(f32). Out f32.
// ---------------------------------------------------------------------------
extern "C" void kernel_launch(void* const* d_in, const int* in_sizes, int n_in,
                              void* d_out, int out_size) {
    const int*   words = (const int*)d_in[0];
    const float* emb   = (const float*)d_in[1];
    const float* w     = (const float*)d_in[2];
    const float* b     = (const float*)d_in[3];
    float*       out   = (float*)d_out;

    cudaFuncSetAttribute(fused_kernel,
                         cudaFuncAttributeMaxDynamicSharedMemorySize, SMEM_BYTES);
    fused_kernel<<<NBLOCKS, NTHREADS, SMEM_BYTES>>>(words, emb, w, b, out);
}

// round 15
// speedup vs baseline: 1.0008x; 1.0008x over previous
#include <cuda_runtime.h>
#include <cuda_fp16.h>

// Problem constants
#define NW 16384   // words
#define WL 16      // word length
#define D  300     // hidden dim
#define DP 320     // padded channel count (zeros in [300,320))
#define NL 128     // letters
#define KS 3       // conv taps

// Single persistent kernel: 296 blocks x 768 threads, 2 CTA/SM (all resident).
#define WPB 24
#define NTHREADS 768
#define B0 118
#define B1 118
#define B2 60
#define NBLOCKS (B0 + B1 + B2)          // 296 = 2 * 148
#define SMEM_BYTES (KS * NL * 128 * 2)  // 96 KB (encode table; phase A aliases it)

// Phase A split
#define PBLK  80    // blocks 0..79: P build, 4 channels each (320 total)
#define PACK0 80    // blocks 80..101: pack (22 * 768 = 16896 >= 16384)
#define PACK1 102

// P-build smem layout (aliased in the 96 KB): w rows + emb half-tile
#define WS_FLOATS (4 * KS * 304)   // 3648
#define ES_STRIDE 129              // conflict-free compute loads (lane = v)
#define ES_FLOATS (150 * ES_STRIDE)  // 19350; WS+ES = 91992 B < 98304 ✓

// Device scratch
__device__ __half g_Ph[KS][NL][DP];  // per-letter conv partials (bias in k=1 tap)
__device__ uint4  g_wpk[NW];         // packed letters: 16 u8 per word

// Grid barrier (epoch-based, replay-safe). Backoff polling avoids the
// single-line poll storm that serialized earlier rounds.
__device__ volatile unsigned g_epoch = 0;
__device__ unsigned g_cnt = 0;

__device__ __forceinline__ void grid_barrier(int tid) {
    __syncthreads();
    if (tid == 0) {
        unsigned e0 = g_epoch;            // read sense BEFORE arriving
        __threadfence();                  // publish this block's global writes
        unsigned old = atomicAdd(&g_cnt, 1);
        if (old == NBLOCKS - 1) {
            g_cnt = 0;
            __threadfence();
            g_epoch = e0 + 1;             // release
        } else {
            unsigned ns = 128;
            while (g_epoch == e0) {
                __nanosleep(ns);
                if (ns < 1024) ns <<= 1;  // exponential backoff, cap 1.0 us
            }
        }
        __threadfence();                  // acquire
    }
    __syncthreads();
}

#define GETL(l) ((lw[(l) >> 2] >> (((l) & 3) * 8)) & 0xFF)

#define INNER_BODY(loidx)                                                        \
    half2 m0 = NEGI, m1 = NEGI, m2 = NEGI, m3 = NEGI;                            \
    _Pragma("unroll")                                                            \
    for (int l = 0; l < WL; ++l) {                                               \
        uint4 a = Pv[(NL + GETL(l)) * 16 + (loidx)];                             \
        half2 h0 = *(half2*)&a.x, h1 = *(half2*)&a.y;                            \
        half2 h2 = *(half2*)&a.z, h3 = *(half2*)&a.w;                            \
        if (l > 0) {                                                             \
            uint4 q = Pv[GETL(l - 1) * 16 + (loidx)];                            \
            h0 = __hadd2(h0, *(half2*)&q.x); h1 = __hadd2(h1, *(half2*)&q.y);    \
            h2 = __hadd2(h2, *(half2*)&q.z); h3 = __hadd2(h3, *(half2*)&q.w);    \
        }                                                                        \
        if (l < WL - 1) {                                                        \
            uint4 q = Pv[(2 * NL + GETL(l + 1)) * 16 + (loidx)];                 \
            h0 = __hadd2(h0, *(half2*)&q.x); h1 = __hadd2(h1, *(half2*)&q.y);    \
            h2 = __hadd2(h2, *(half2*)&q.z); h3 = __hadd2(h3, *(half2*)&q.w);    \
        }                                                                        \
        m0 = __hmax2(m0, h0); m1 = __hmax2(m1, h1);                              \
        m2 = __hmax2(m2, h2); m3 = __hmax2(m3, h3);                              \
    }

__global__ __launch_bounds__(NTHREADS, 2) void fused_kernel(const int* __restrict__ words,
                                                            const float* __restrict__ emb,
                                                            const float* __restrict__ w,
                                                            const float* __restrict__ bias,
                                                            float* __restrict__ out) {
    extern __shared__ uint4 Pv[];  // 96 KB; phase A aliases it
    const int b   = blockIdx.x;
    const int tid = threadIdx.x;

    // ================= PHASE A: P build (with inline transpose) + pack ======
    if (b < PBLK) {
        float* ws = (float*)Pv;         // [4][KS][304]
        float* es = ws + WS_FLOATS;     // [150][ES_STRIDE]: es[i_local*129 + v]

        const int ob = b * 4;
        const int j  = tid >> 7;        // 0..5; only 0..3 compute
        const int v  = tid & 127;
        const int o  = ob + j;

        // Stage w rows de-interleaved: ws[jj][k][i] (coalesced gmem reads)
        for (int t = tid; t < 4 * D * KS; t += NTHREADS) {
            int jj = t / (D * KS), r = t % (D * KS);
            int oo = ob + jj;
            ws[(jj * KS + r % 3) * 304 + r / 3] = (oo < D) ? w[oo * D * KS + r] : 0.f;
        }

        float a0 = 0.f, a1 = 0.f, a2 = 0.f;
#pragma unroll
        for (int rnd = 0; rnd < 2; ++rnd) {
            const int i0 = rnd * 150;
            __syncthreads();
            // Transpose-stage emb[:, i0:i0+150): coalesced float2 reads along
            // rows; scattered stores (~2-way bank conflict, tiny volume).
            for (int idx = tid; idx < NL * 75; idx += NTHREADS) {
                int vv = idx / 75, c = idx % 75;
                float2 e = *(const float2*)(emb + vv * D + i0 + c * 2);
                es[(c * 2 + 0) * ES_STRIDE + vv] = e.x;
                es[(c * 2 + 1) * ES_STRIDE + vv] = e.y;
            }
            __syncthreads();
            if (j < 4) {
                const float* w0p = ws + (j * KS + 0) * 304 + i0;
                const float* w1p = ws + (j * KS + 1) * 304 + i0;
                const float* w2p = ws + (j * KS + 2) * 304 + i0;
#pragma unroll 5
                for (int i = 0; i < 150; i += 2) {
                    float e0 = es[(i + 0) * ES_STRIDE + v];   // conflict-free
                    float e1 = es[(i + 1) * ES_STRIDE + v];
                    float2 w0 = *(const float2*)(w0p + i);    // uniform bcast
                    float2 w1 = *(const float2*)(w1p + i);
                    float2 w2 = *(const float2*)(w2p + i);
                    a0 = fmaf(e0, w0.x, a0); a1 = fmaf(e0, w1.x, a1); a2 = fmaf(e0, w2.x, a2);
                    a0 = fmaf(e1, w0.y, a0); a1 = fmaf(e1, w1.y, a1); a2 = fmaf(e1, w2.y, a2);
                }
            }
        }
        if (j < 4) {
            bool real = (o < D);
            float bv = real ? bias[o] : 0.f;
            g_Ph[0][v][o] = __float2half(real ? a0 : 0.f);
            g_Ph[1][v][o] = __float2half(real ? (a1 + bv) : 0.f);  // bias in k=1
            g_Ph[2][v][o] = __float2half(real ? a2 : 0.f);
        }
    } else if (b < PACK1) {
        const int n = (b - PACK0) * NTHREADS + tid;
        if (n < NW) {
            unsigned r0 = 0, r1 = 0, r2 = 0, r3 = 0;
#pragma unroll
            for (int l = 0; l < 4; ++l)  r0 |= ((unsigned)words[l * NW + n] & 0xFF) << (l * 8);
#pragma unroll
            for (int l = 4; l < 8; ++l)  r1 |= ((unsigned)words[l * NW + n] & 0xFF) << ((l - 4) * 8);
#pragma unroll
            for (int l = 8; l < 12; ++l) r2 |= ((unsigned)words[l * NW + n] & 0xFF) << ((l - 8) * 8);
#pragma unroll
            for (int l = 12; l < 16; ++l) r3 |= ((unsigned)words[l * NW + n] & 0xFF) << ((l - 12) * 8);
            g_wpk[n] = make_uint4(r0, r1, r2, r3);
        }
    }
    // blocks >= PACK1: straight to the barrier

    grid_barrier(tid);   // the ONLY grid-wide sync

    // ======================= PHASE B: ENCODE =======================
    int slice, lb, nb;
    if (b < B0)           { slice = 0; lb = b;           nb = B0; }
    else if (b < B0 + B1) { slice = 1; lb = b - B0;      nb = B1; }
    else                  { slice = 2; lb = b - B0 - B1; nb = B2; }
    const int c0 = slice * 128;
    const int nchunk = (slice == 2) ? 8 : 16;

    const uint4* gP = (const uint4*)g_Ph;  // row stride DP/8 = 40 uint4
    for (int idx = tid; idx < KS * NL * nchunk; idx += NTHREADS) {
        int r = idx / nchunk, c = idx % nchunk;
        Pv[r * 16 + c] = gP[r * (DP / 8) + slice * 16 + c];
    }
    __syncthreads();

    const int lane  = tid & 31;
    const int wid   = tid >> 5;
    const int wsl   = lb * WPB + wid;
    const int nwarp = nb * WPB;

    const __half NH = __ushort_as_half((unsigned short)0xFC00);  // -inf
    const half2 NEGI = __halves2half2(NH, NH);

    if (slice < 2) {
        // ---- 128-ch slice: 2 words per warp (16-lane halves) ----
        const int lo   = lane & 15;
        const int half = lane >> 4;
        const int ch   = c0 + lo * 8;

        uint4 pk = g_wpk[2 * wsl + half];
        for (int p = wsl; p < NW / 2; p += nwarp) {
            const int pn = p + nwarp;
            uint4 nxt = make_uint4(0, 0, 0, 0);
            if (pn < NW / 2) nxt = g_wpk[2 * pn + half];

            unsigned lw[4] = {pk.x, pk.y, pk.z, pk.w};
            const int gw = 2 * p + half;

            INNER_BODY(lo)

            float2 f0 = __half22float2(m0), f1 = __half22float2(m1);
            float2 f2 = __half22float2(m2), f3 = __half22float2(m3);
            float* op = out + (size_t)gw * D + ch;
            float4 r;
            r.x = fmaxf(f0.x, 0.f); r.y = fmaxf(f0.y, 0.f);
            r.z = fmaxf(f1.x, 0.f); r.w = fmaxf(f1.y, 0.f);
            *(float4*)op = r;
            r.x = fmaxf(f2.x, 0.f); r.y = fmaxf(f2.y, 0.f);
            r.z = fmaxf(f3.x, 0.f); r.w = fmaxf(f3.y, 0.f);
            *(float4*)(op + 4) = r;

            pk = nxt;
        }
    } else {
        // ---- 64-ch slice (channels 256..299 real): 4 words per warp ----
        const int lo8 = lane & 7;
        const int g   = lane >> 3;
        const int ch  = c0 + lo8 * 8;  // 256..312

        uint4 pk = g_wpk[4 * wsl + g];
        for (int p = wsl; p < NW / 4; p += nwarp) {
            const int pn = p + nwarp;
            uint4 nxt = make_uint4(0, 0, 0, 0);
            if (pn < NW / 4) nxt = g_wpk[4 * pn + g];

            unsigned lw[4] = {pk.x, pk.y, pk.z, pk.w};
            const int gw = 4 * p + g;

            INNER_BODY(lo8)

            float2 f0 = __half22float2(m0), f1 = __half22float2(m1);
            float2 f2 = __half22float2(m2), f3 = __half22float2(m3);
            float* op = out + (size_t)gw * D + ch;
            if (ch < D) {
                float4 r;
                r.x = fmaxf(f0.x, 0.f); r.y = fmaxf(f0.y, 0.f);
                r.z = fmaxf(f1.x, 0.f); r.w = fmaxf(f1.y, 0.f);
                *(float4*)op = r;
            }
            if (ch + 4 < D) {
                float4 r;
                r.x = fmaxf(f2.x, 0.f); r.y = fmaxf(f2.y, 0.f);
                r.z = fmaxf(f3.x, 0.f); r.w = fmaxf(f3.y, 0.f);
                *(float4*)(op + 4) = r;
            }
            pk = nxt;
        }
    }
}

// ---------------------------------------------------------------------------
// Launch. Inputs: words(int32), emb(f32), conv_w(f32), conv_b(f32). Out f32.
// ---------------------------------------------------------------------------
extern "C" void kernel_launch(void* const* d_in, const int* in_sizes, int n_in,
                              void* d_out, int out_size) {
    const int*   words = (const int*)d_in[0];
    const float* emb   = (const float*)d_in[1];
    const float* w     = (const float*)d_in[2];
    const float* b     = (const float*)d_in[3];
    float*       out   = (float*)d_out;

    cudaFuncSetAttribute(fused_kernel,
                         cudaFuncAttributeMaxDynamicSharedMemorySize, SMEM_BYTES);
    fused_kernel<<<NBLOCKS, NTHREADS, SMEM_BYTES>>>(words, emb, w, b, out);
}

// round 16
// speedup vs baseline: 1.0544x; 1.0536x over previous
#include <cuda_runtime.h>
#include <cuda_fp16.h>

// Problem constants
#define NW 16384   // words
#define WL 16      // word length
#define D  300     // hidden dim
#define DP 320     // padded channel count (zeros in [300,320))
#define NL 128     // letters
#define KS 3       // conv taps

// Encode config: slices 0/1 = 128 ch (2 words/warp), slice 2 = 64 ch
// (4 words/warp). 768 threads/CTA, 2 CTA/SM -> 48 warps/SM.
#define WPB 24
#define ENC_THREADS 768
#define B0 118
#define B1 118
#define B2 60
#define ENC_BLOCKS (B0 + B1 + B2)           // 296 = 2 CTA/SM * 148 SMs
#define ENC_SMEM (KS * NL * 128 * 2)        // 96 KB

// Fused prep: blocks [0,32) pack words, blocks [32,112) build P
// (80 blocks x 4 channels = 320). 112 blocks = ONE wave @ 1 CTA/SM.
#define PACKB 32
#define PREP_BLOCKS 112
#define PREP_THREADS 512
#define ES_STRIDE 308   // floats; conflict-free LDS.128 (77 quads, gcd(77,8)=1)
#define PREP_SMEM ((NL * ES_STRIDE + 4 * KS * 304) * 4)  // 172288 B

// Device scratch
__device__ __half g_Ph[KS][NL][DP];  // per-letter conv partials (bias in k=1 tap)
__device__ uint4  g_wpk[NW];         // packed letters: 16 u8 per word

// packed-f32x2 FMA (FFMA2) — PTX only
__device__ __forceinline__ void fma2(unsigned long long& d,
                                     unsigned long long a, unsigned long long b) {
    asm("fma.rn.f32x2 %0, %1, %2, %0;" : "+l"(d) : "l"(a), "l"(b));
}
__device__ __forceinline__ float2 unpack2(unsigned long long x) {
    float2 f;
    asm("mov.b64 {%0, %1}, %2;" : "=f"(f.x), "=f"(f.y) : "l"(x));
    return f;
}

// ---------------------------------------------------------------------------
// Kernel 1 (fused prep, ONE wave) — identical to the R11 measured version.
// ---------------------------------------------------------------------------
__global__ __launch_bounds__(PREP_THREADS) void prep_kernel(const int* __restrict__ words,
                                                            const float* __restrict__ emb,
                                                            const float* __restrict__ w,
                                                            const float* __restrict__ bias) {
    if (blockIdx.x < PACKB) {
        const int n = blockIdx.x * PREP_THREADS + threadIdx.x;
        unsigned r0 = 0, r1 = 0, r2 = 0, r3 = 0;
#pragma unroll
        for (int l = 0; l < 4; ++l)  r0 |= ((unsigned)words[l * NW + n] & 0xFF) << (l * 8);
#pragma unroll
        for (int l = 4; l < 8; ++l)  r1 |= ((unsigned)words[l * NW + n] & 0xFF) << ((l - 4) * 8);
#pragma unroll
        for (int l = 8; l < 12; ++l) r2 |= ((unsigned)words[l * NW + n] & 0xFF) << ((l - 8) * 8);
#pragma unroll
        for (int l = 12; l < 16; ++l) r3 |= ((unsigned)words[l * NW + n] & 0xFF) << ((l - 12) * 8);
        g_wpk[n] = make_uint4(r0, r1, r2, r3);
        return;
    }

    // ---- P branch: 4 output channels per block ----
    extern __shared__ float sm[];
    float* es = sm;                       // [128][ES_STRIDE]
    float* ws = sm + NL * ES_STRIDE;      // [4][KS][304]

    const int ob = (blockIdx.x - PACKB) * 4;
    const int j  = threadIdx.x >> 7;      // 0..3 (channel within block)
    const int v  = threadIdx.x & 127;     // letter
    const int o  = ob + j;

    const float4* e4 = (const float4*)emb;
    for (int idx = threadIdx.x; idx < NL * (D / 4); idx += PREP_THREADS) {
        int vv = idx / (D / 4), c = idx % (D / 4);
        *(float4*)&es[vv * ES_STRIDE + c * 4] = e4[idx];
    }
    for (int t = threadIdx.x; t < 4 * D * KS; t += PREP_THREADS) {
        int jj = t / (D * KS), r = t % (D * KS);
        int oo = ob + jj;
        ws[(jj * KS + r % 3) * 304 + r / 3] = (oo < D) ? w[oo * D * KS + r] : 0.f;
    }
    __syncthreads();

    typedef unsigned long long u64;
    u64 a0l = 0, a0h = 0, a1l = 0, a1h = 0, a2l = 0, a2h = 0;
    const float* ev  = es + v * ES_STRIDE;
    const float* w0p = ws + (j * KS + 0) * 304;
    const float* w1p = ws + (j * KS + 1) * 304;
    const float* w2p = ws + (j * KS + 2) * 304;
#pragma unroll 5
    for (int i = 0; i < D; i += 4) {
        ulonglong2 e2 = *(const ulonglong2*)(ev + i);
        ulonglong2 w0 = *(const ulonglong2*)(w0p + i);
        ulonglong2 w1 = *(const ulonglong2*)(w1p + i);
        ulonglong2 w2 = *(const ulonglong2*)(w2p + i);
        fma2(a0l, e2.x, w0.x); fma2(a0h, e2.y, w0.y);
        fma2(a1l, e2.x, w1.x); fma2(a1h, e2.y, w1.y);
        fma2(a2l, e2.x, w2.x); fma2(a2h, e2.y, w2.y);
    }
    float2 p0 = unpack2(a0l), q0 = unpack2(a0h);
    float2 p1 = unpack2(a1l), q1 = unpack2(a1h);
    float2 p2 = unpack2(a2l), q2 = unpack2(a2h);
    float a0 = (p0.x + p0.y) + (q0.x + q0.y);
    float a1 = (p1.x + p1.y) + (q1.x + q1.y);
    float a2 = (p2.x + p2.y) + (q2.x + q2.y);

    bool real = (o < D);
    float bv = real ? bias[o] : 0.f;
    g_Ph[0][v][o] = __float2half(real ? a0 : 0.f);
    g_Ph[1][v][o] = __float2half(real ? (a1 + bv) : 0.f);  // bias folded into k=1
    g_Ph[2][v][o] = __float2half(real ? a2 : 0.f);
}

// ---------------------------------------------------------------------------
// Kernel 2: encode with ROLLING-ADDRESS inner loop. Row stride in smem is
// 256 B; the three tap-tables sit at byte offsets 0 / 32768 / 65536. Per
// position: ONE letter extract + ONE IMAD; the k=0 and k=1 loads reuse the
// address registers from previous positions via LDS reg+immediate.
// ---------------------------------------------------------------------------
#define GETL(l) ((lw[(l) >> 2] >> (((l) & 3) * 8)) & 0xFF)

#define INNER_BODY(LOB)                                                          \
    half2 m0 = NEGI, m1 = NEGI, m2 = NEGI, m3 = NEGI;                            \
    {                                                                            \
        const char* Pb = (const char*)Pv;                                        \
        unsigned a0p = 0;                                                        \
        unsigned a1p = (lw[0] & 0xFF) * 256 + (LOB);                             \
        _Pragma("unroll")                                                        \
        for (int l = 0; l < WL; ++l) {                                           \
            unsigned a2p = (l < WL - 1) ? GETL(l + 1) * 256 + (LOB) : 0;         \
            uint4 a = *(const uint4*)(Pb + 32768 + a1p);  /* k=1, this char */   \
            half2 h0 = *(half2*)&a.x, h1 = *(half2*)&a.y;                        \
            half2 h2 = *(half2*)&a.z, h3 = *(half2*)&a.w;                        \
            if (l > 0) {                                                         \
                uint4 q = *(const uint4*)(Pb + a0p);       /* k=0, prev */       \
                h0 = __hadd2(h0, *(half2*)&q.x); h1 = __hadd2(h1, *(half2*)&q.y);\
                h2 = __hadd2(h2, *(half2*)&q.z); h3 = __hadd2(h3, *(half2*)&q.w);\
            }                                                                    \
            if (l < WL - 1) {                                                    \
                uint4 q = *(const uint4*)(Pb + 65536 + a2p); /* k=2, next */     \
                h0 = __hadd2(h0, *(half2*)&q.x); h1 = __hadd2(h1, *(half2*)&q.y);\
                h2 = __hadd2(h2, *(half2*)&q.z); h3 = __hadd2(h3, *(half2*)&q.w);\
            }                                                                    \
            m0 = __hmax2(m0, h0); m1 = __hmax2(m1, h1);                          \
            m2 = __hmax2(m2, h2); m3 = __hmax2(m3, h3);                          \
            a0p = a1p; a1p = a2p;                                                \
        }                                                                        \
    }

__global__ __launch_bounds__(ENC_THREADS, 2) void encode_kernel(float* __restrict__ out) {
    extern __shared__ uint4 Pv[];  // [KS*NL rows][16 uint4], row stride 256 B

    int b = blockIdx.x;
    int slice, lb, nb;
    if (b < B0)           { slice = 0; lb = b;           nb = B0; }
    else if (b < B0 + B1) { slice = 1; lb = b - B0;      nb = B1; }
    else                  { slice = 2; lb = b - B0 - B1; nb = B2; }
    const int c0 = slice * 128;
    const int nchunk = (slice == 2) ? 8 : 16;  // valid uint4 chunks per row

    const uint4* gP = (const uint4*)g_Ph;  // row stride DP/8 = 40 uint4
    for (int idx = threadIdx.x; idx < KS * NL * nchunk; idx += ENC_THREADS) {
        int r = idx / nchunk, c = idx % nchunk;
        Pv[r * 16 + c] = gP[r * (DP / 8) + slice * 16 + c];
    }
    __syncthreads();

    const int lane  = threadIdx.x & 31;
    const int wid   = threadIdx.x >> 5;
    const int wsl   = lb * WPB + wid;
    const int nwarp = nb * WPB;

    const __half NH = __ushort_as_half((unsigned short)0xFC00);  // -inf
    const half2 NEGI = __halves2half2(NH, NH);

    if (slice < 2) {
        // ---- 128-ch slice: 2 words per warp (16-lane halves) ----
        const int lo   = lane & 15;
        const int half = lane >> 4;
        const int ch   = c0 + lo * 8;
        const unsigned LOB = lo * 16;   // byte offset within row

        uint4 pk = g_wpk[2 * wsl + half];
        for (int p = wsl; p < NW / 2; p += nwarp) {
            const int pn = p + nwarp;
            uint4 nxt = make_uint4(0, 0, 0, 0);
            if (pn < NW / 2) nxt = g_wpk[2 * pn + half];

            unsigned lw[4] = {pk.x, pk.y, pk.z, pk.w};
            const int gw = 2 * p + half;

            INNER_BODY(LOB)

            float2 f0 = __half22float2(m0), f1 = __half22float2(m1);
            float2 f2 = __half22float2(m2), f3 = __half22float2(m3);
            float* op = out + (size_t)gw * D + ch;
            float4 r;
            r.x = fmaxf(f0.x, 0.f); r.y = fmaxf(f0.y, 0.f);
            r.z = fmaxf(f1.x, 0.f); r.w = fmaxf(f1.y, 0.f);
            *(float4*)op = r;
            r.x = fmaxf(f2.x, 0.f); r.y = fmaxf(f2.y, 0.f);
            r.z = fmaxf(f3.x, 0.f); r.w = fmaxf(f3.y, 0.f);
            *(float4*)(op + 4) = r;

            pk = nxt;
        }
    } else {
        // ---- 64-ch slice (channels 256..299 real): 4 words per warp ----
        const int lo8 = lane & 7;
        const int g   = lane >> 3;
        const int ch  = c0 + lo8 * 8;  // 256..312
        const unsigned LOB = lo8 * 16;

        uint4 pk = g_wpk[4 * wsl + g];
        for (int p = wsl; p < NW / 4; p += nwarp) {
            const int pn = p + nwarp;
            uint4 nxt = make_uint4(0, 0, 0, 0);
            if (pn < NW / 4) nxt = g_wpk[4 * pn + g];

            unsigned lw[4] = {pk.x, pk.y, pk.z, pk.w};
            const int gw = 4 * p + g;

            INNER_BODY(LOB)

            float2 f0 = __half22float2(m0), f1 = __half22float2(m1);
            float2 f2 = __half22float2(m2), f3 = __half22float2(m3);
            float* op = out + (size_t)gw * D + ch;
            if (ch < D) {
                float4 r;
                r.x = fmaxf(f0.x, 0.f); r.y = fmaxf(f0.y, 0.f);
                r.z = fmaxf(f1.x, 0.f); r.w = fmaxf(f1.y, 0.f);
                *(float4*)op = r;
            }
            if (ch + 4 < D) {
                float4 r;
                r.x = fmaxf(f2.x, 0.f); r.y = fmaxf(f2.y, 0.f);
                r.z = fmaxf(f3.x, 0.f); r.w = fmaxf(f3.y, 0.f);
                *(float4*)(op + 4) = r;
            }
            pk = nxt;
        }
    }
}

// ---------------------------------------------------------------------------
// Launch. Inputs: words(int32), emb(f32), conv_w(f32), conv_b(f32). Out f32.
// ---------------------------------------------------------------------------
extern "C" void kernel_launch(void* const* d_in, const int* in_sizes, int n_in,
                              void* d_out, int out_size) {
    const int*   words = (const int*)d_in[0];
    const float* emb   = (const float*)d_in[1];
    const float* w     = (const float*)d_in[2];
    const float* b     = (const float*)d_in[3];
    float*       out   = (float*)d_out;

    cudaFuncSetAttribute(prep_kernel,
                         cudaFuncAttributeMaxDynamicSharedMemorySize, PREP_SMEM);
    prep_kernel<<<PREP_BLOCKS, PREP_THREADS, PREP_SMEM>>>(words, emb, w, b);

    cudaFuncSetAttribute(encode_kernel,
                         cudaFuncAttributeMaxDynamicSharedMemorySize, ENC_SMEM);
    encode_kernel<<<ENC_BLOCKS, ENC_THREADS, ENC_SMEM>>>(out);
}